// round 14
// baseline (speedup 1.0000x reference)
#include <cuda_runtime.h>
#include <math.h>

// Problem constants
#define BATCH 2
#define TT    2048
#define CC    1024
#define NH    16
#define HD    64    // head size
#define BQ    64    // q/k tile in attention

// Device-global scratch (allocation-free rule): Q/K/V in [B,H,T,D], Y in [B,T,C]
__device__ float g_q[BATCH * NH * TT * HD];
__device__ float g_k[BATCH * NH * TT * HD];
__device__ float g_v[BATCH * NH * TT * HD];
__device__ float g_y[BATCH * TT * CC];

// ---------------------------------------------------------------------------
// SGEMM: out = A[M,K] @ W[K,N] + bias[N]
// MODE 0: A = x (param), scatter epilogue -> g_q/g_k/g_v (q scaled by 0.125)
// MODE 1: A = g_y (internal), dense epilogue -> out
// BM=BN=128, BK=8, TM=TN=8, 256 threads. All dims divisible -> no bounds checks.
// ---------------------------------------------------------------------------
template <int MODE>
__global__ void __launch_bounds__(256) sgemm_kernel(
    const float* __restrict__ A_in,
    const float* __restrict__ W,
    const float* __restrict__ bias,
    float* __restrict__ out,
    int M, int N, int K)
{
    constexpr int BM = 128, BN = 128, BK = 8, TM = 8, TN = 8;
    __shared__ float As[BK][BM];
    __shared__ float Bs[BK][BN];

    const int tid = threadIdx.x;
    const int cRow = blockIdx.y;   // block row  (M)
    const int cCol = blockIdx.x;   // block col  (N)

    const int threadCol = tid % (BN / TN);  // 0..15
    const int threadRow = tid / (BN / TN);  // 0..15

    // A tile loader: 128 rows x 8 cols, one float4 per thread
    const int innerRowA = tid >> 1;          // 0..127
    const int innerColA = (tid & 1) * 4;     // 0 or 4
    // B tile loader: 8 rows x 128 cols, one float4 per thread
    const int innerRowB = tid >> 5;          // 0..7
    const int innerColB = (tid & 31) * 4;    // 0..124

    const float* A = (MODE == 1) ? g_y : A_in;
    const float* Ap = A + (size_t)cRow * BM * K;
    const float* Bp = W + (size_t)cCol * BN;

    float acc[TM][TN];
    #pragma unroll
    for (int i = 0; i < TM; i++)
        #pragma unroll
        for (int j = 0; j < TN; j++) acc[i][j] = 0.f;

    for (int k0 = 0; k0 < K; k0 += BK) {
        float4 a4 = *(const float4*)(Ap + (size_t)innerRowA * K + k0 + innerColA);
        As[innerColA + 0][innerRowA] = a4.x;
        As[innerColA + 1][innerRowA] = a4.y;
        As[innerColA + 2][innerRowA] = a4.z;
        As[innerColA + 3][innerRowA] = a4.w;
        *(float4*)&Bs[innerRowB][innerColB] =
            *(const float4*)(Bp + (size_t)(k0 + innerRowB) * N + innerColB);
        __syncthreads();

        #pragma unroll
        for (int k = 0; k < BK; k++) {
            float4 m0 = *(const float4*)&As[k][threadRow * TM];
            float4 m1 = *(const float4*)&As[k][threadRow * TM + 4];
            float4 n0 = *(const float4*)&Bs[k][threadCol * TN];
            float4 n1 = *(const float4*)&Bs[k][threadCol * TN + 4];
            float rm[TM] = {m0.x, m0.y, m0.z, m0.w, m1.x, m1.y, m1.z, m1.w};
            float rn[TN] = {n0.x, n0.y, n0.z, n0.w, n1.x, n1.y, n1.z, n1.w};
            #pragma unroll
            for (int i = 0; i < TM; i++)
                #pragma unroll
                for (int j = 0; j < TN; j++)
                    acc[i][j] += rm[i] * rn[j];
        }
        __syncthreads();
    }

    // Epilogue
    #pragma unroll
    for (int i = 0; i < TM; i++) {
        const int r = cRow * BM + threadRow * TM + i;
        const int nbase = cCol * BN + threadCol * TN;
        if (MODE == 1) {
            #pragma unroll
            for (int j = 0; j < TN; j++)
                out[(size_t)r * N + nbase + j] = acc[i][j] + bias[nbase + j];
        } else {
            // n in [0,3072): which = n>>10 (q/k/v), head = (n&1023)>>6, d = n&63
            // 8-col chunk never crosses a 64-boundary -> which/head constant per thread
            const int b = r >> 11, t = r & 2047;
            const int which = nbase >> 10;
            const int c = nbase & 1023;
            const int h = c >> 6;
            const int dbase = c & 63;
            const int idx = (((b * NH + h) * TT + t) * HD) + dbase;
            if (which == 0) {
                #pragma unroll
                for (int j = 0; j < TN; j++)
                    g_q[idx + j] = (acc[i][j] + bias[nbase + j]) * 0.125f; // fold 1/sqrt(64)
            } else if (which == 1) {
                #pragma unroll
                for (int j = 0; j < TN; j++)
                    g_k[idx + j] = acc[i][j] + bias[nbase + j];
            } else {
                #pragma unroll
                for (int j = 0; j < TN; j++)
                    g_v[idx + j] = acc[i][j] + bias[nbase + j];
            }
        }
    }
}

// ---------------------------------------------------------------------------
// Causal flash attention, fp32 SIMT.
// grid = (32 q-tiles, 32 b*h), block = 256 (16x16 thread grid, 4x4 per thread)
// smem: Qs(16K) + KVs(16K, K then V) + Ps(16K) = 48KB static.
// Online softmax per-row state kept in registers, reduced with 16-lane shuffles.
// ---------------------------------------------------------------------------
__global__ void __launch_bounds__(256) attn_kernel()
{
    __shared__ float Qs[BQ * HD];
    __shared__ float KVs[BQ * HD];
    __shared__ float Ps[BQ * BQ];

    const int it  = blockIdx.x;     // q tile 0..31
    const int bh  = blockIdx.y;     // 0..31
    const int tid = threadIdx.x;
    const int tx  = tid & 15;       // column group (k-col / d-col)
    const int ty  = tid >> 4;       // row group (q-row)

    const float* Qg = g_q + ((size_t)bh * TT + it * BQ) * HD;

    // Q tile is one contiguous 16KB block in gmem
    #pragma unroll
    for (int i = tid; i < BQ * HD / 4; i += 256)
        ((float4*)Qs)[i] = ((const float4*)Qg)[i];

    float O[4][4];
    #pragma unroll
    for (int i = 0; i < 4; i++)
        #pragma unroll
        for (int j = 0; j < 4; j++) O[i][j] = 0.f;
    float mrow[4] = {-INFINITY, -INFINITY, -INFINITY, -INFINITY};
    float lrow[4] = {0.f, 0.f, 0.f, 0.f};

    for (int jt = 0; jt <= it; jt++) {
        __syncthreads();  // prev PV done (KVs, Ps reusable); also first-iter Q load fence
        const float* Kg = g_k + ((size_t)bh * TT + jt * BQ) * HD;
        #pragma unroll
        for (int i = tid; i < BQ * HD / 4; i += 256)
            ((float4*)KVs)[i] = ((const float4*)Kg)[i];
        __syncthreads();

        // S = (Q*scale) K^T  for this 64x64 tile; 4x4 per thread
        float s[4][4];
        #pragma unroll
        for (int i = 0; i < 4; i++)
            #pragma unroll
            for (int j = 0; j < 4; j++) s[i][j] = 0.f;
        #pragma unroll
        for (int kk = 0; kk < HD; kk += 4) {
            float4 a4[4], b4[4];
            #pragma unroll
            for (int i = 0; i < 4; i++)
                a4[i] = *(const float4*)&Qs[(4 * ty + i) * HD + kk];
            #pragma unroll
            for (int j = 0; j < 4; j++)
                b4[j] = *(const float4*)&KVs[(4 * tx + j) * HD + kk];
            #pragma unroll
            for (int i = 0; i < 4; i++)
                #pragma unroll
                for (int j = 0; j < 4; j++)
                    s[i][j] += a4[i].x * b4[j].x + a4[i].y * b4[j].y +
                               a4[i].z * b4[j].z + a4[i].w * b4[j].w;
        }

        // causal mask on the diagonal tile
        if (jt == it) {
            #pragma unroll
            for (int i = 0; i < 4; i++)
                #pragma unroll
                for (int j = 0; j < 4; j++)
                    if ((4 * tx + j) > (4 * ty + i)) s[i][j] = -INFINITY;
        }

        // Online softmax. Row r = 4*ty+i is owned by the 16 lanes sharing ty
        // (contiguous 16-lane group within a warp) -> xor-shuffles 8,4,2,1.
        #pragma unroll
        for (int i = 0; i < 4; i++) {
            float mx = fmaxf(fmaxf(s[i][0], s[i][1]), fmaxf(s[i][2], s[i][3]));
            #pragma unroll
            for (int o = 8; o >= 1; o >>= 1)
                mx = fmaxf(mx, __shfl_xor_sync(0xffffffffu, mx, o));
            float mnew = fmaxf(mrow[i], mx);
            float corr = __expf(mrow[i] - mnew);
            float p0 = __expf(s[i][0] - mnew);
            float p1 = __expf(s[i][1] - mnew);
            float p2 = __expf(s[i][2] - mnew);
            float p3 = __expf(s[i][3] - mnew);
            float sum = p0 + p1 + p2 + p3;
            #pragma unroll
            for (int o = 8; o >= 1; o >>= 1)
                sum += __shfl_xor_sync(0xffffffffu, sum, o);
            lrow[i] = lrow[i] * corr + sum;
            mrow[i] = mnew;
            #pragma unroll
            for (int j = 0; j < 4; j++) O[i][j] *= corr;
            *(float4*)&Ps[(4 * ty + i) * BQ + 4 * tx] = make_float4(p0, p1, p2, p3);
        }
        __syncthreads();  // Ps complete; all K reads done -> KVs free for V

        const float* Vg = g_v + ((size_t)bh * TT + jt * BQ) * HD;
        #pragma unroll
        for (int i = tid; i < BQ * HD / 4; i += 256)
            ((float4*)KVs)[i] = ((const float4*)Vg)[i];
        __syncthreads();

        // O += P @ V
        #pragma unroll
        for (int kk = 0; kk < BQ; kk += 4) {
            float4 p4[4], v4[4];
            #pragma unroll
            for (int i = 0; i < 4; i++)
                p4[i] = *(const float4*)&Ps[(4 * ty + i) * BQ + kk];
            #pragma unroll
            for (int k2 = 0; k2 < 4; k2++)
                v4[k2] = *(const float4*)&KVs[(kk + k2) * HD + 4 * tx];
            #pragma unroll
            for (int i = 0; i < 4; i++) {
                O[i][0] += p4[i].x * v4[0].x + p4[i].y * v4[1].x + p4[i].z * v4[2].x + p4[i].w * v4[3].x;
                O[i][1] += p4[i].x * v4[0].y + p4[i].y * v4[1].y + p4[i].z * v4[2].y + p4[i].w * v4[3].y;
                O[i][2] += p4[i].x * v4[0].z + p4[i].y * v4[1].z + p4[i].z * v4[2].z + p4[i].w * v4[3].z;
                O[i][3] += p4[i].x * v4[0].w + p4[i].y * v4[1].w + p4[i].z * v4[2].w + p4[i].w * v4[3].w;
            }
        }
    }

    // Write y in [B,T,C] layout for the proj GEMM
    const int b = bh >> 4, h = bh & 15;
    #pragma unroll
    for (int i = 0; i < 4; i++) {
        const int tq = it * BQ + 4 * ty + i;
        const float linv = 1.f / lrow[i];
        float* yp = g_y + ((size_t)b * TT + tq) * CC + h * HD + 4 * tx;
        *(float4*)yp = make_float4(O[i][0] * linv, O[i][1] * linv,
                                   O[i][2] * linv, O[i][3] * linv);
    }
}

// ---------------------------------------------------------------------------
extern "C" void kernel_launch(void* const* d_in, const int* in_sizes, int n_in,
                              void* d_out, int out_size)
{
    const float* x      = (const float*)d_in[0];  // [2,2048,1024]
    const float* w_attn = (const float*)d_in[1];  // [1024,3072]
    const float* b_attn = (const float*)d_in[2];  // [3072]
    const float* w_proj = (const float*)d_in[3];  // [1024,1024]
    const float* b_proj = (const float*)d_in[4];  // [1024]
    float* out = (float*)d_out;                   // [2,2048,1024]

    const int M = BATCH * TT;      // 4096

    // 1) QKV projection + scatter to [B,H,T,D] (q pre-scaled)
    {
        dim3 grid(3 * CC / 128, M / 128);  // (24, 32)
        sgemm_kernel<0><<<grid, 256>>>(x, w_attn, b_attn, nullptr, M, 3 * CC, CC);
    }
    // 2) Causal flash attention
    {
        dim3 grid(TT / BQ, BATCH * NH);    // (32, 32)
        attn_kernel<<<grid, 256>>>();
    }
    // 3) Output projection
    {
        dim3 grid(CC / 128, M / 128);      // (8, 32)
        sgemm_kernel<1><<<grid, 256>>>(nullptr, w_proj, b_proj, out, M, CC, CC);
    }
}

// round 15
// speedup vs baseline: 1.2038x; 1.2038x over previous
#include <cuda_runtime.h>
#include <cuda_bf16.h>
#include <math.h>
#include <stdint.h>

#define BATCH 2
#define TT    2048
#define CC    1024
#define NH    16
#define HD    64
#define BQ    64
#define KDIM  1024
#define MROWS 4096

// ---------------------------------------------------------------------------
// Device-global scratch — round-1 footprint. NEVER passed from host code;
// all references are device-side (the proven-passing pattern).
// ---------------------------------------------------------------------------
__device__ float g_q[BATCH * NH * TT * HD];
__device__ float g_k[BATCH * NH * TT * HD];
__device__ float g_v[BATCH * NH * TT * HD];
__device__ float g_y[BATCH * TT * CC];

// ---------------------------------------------------------------------------
// Helpers (scalar-only interfaces)
// ---------------------------------------------------------------------------
__device__ __forceinline__ uint32_t cvta_smem(const void* p) {
    uint32_t a;
    asm("{ .reg .u64 t; cvta.to.shared.u64 t, %1; cvt.u32.u64 %0, t; }"
        : "=r"(a) : "l"(p));
    return a;
}
// pack two floats -> bf16x2 (first arg in low half)
__device__ __forceinline__ uint32_t fpack(float lo, float hi) {
    uint32_t r;
    asm("cvt.rn.bf16x2.f32 %0, %2, %1;" : "=r"(r) : "f"(lo), "f"(hi));
    return r;
}
__device__ __forceinline__ float bflow(uint32_t u)  { return __uint_as_float(u << 16); }
__device__ __forceinline__ float bfhigh(uint32_t u) { return __uint_as_float(u & 0xffff0000u); }

__device__ __forceinline__ void ldsm4(uint32_t addr, uint32_t& r0, uint32_t& r1,
                                      uint32_t& r2, uint32_t& r3) {
    asm volatile("ldmatrix.sync.aligned.m8n8.x4.shared.b16 {%0,%1,%2,%3}, [%4];"
                 : "=r"(r0), "=r"(r1), "=r"(r2), "=r"(r3) : "r"(addr) : "memory");
}
__device__ __forceinline__ void mma16816(float& c0, float& c1, float& c2, float& c3,
                                         uint32_t a0, uint32_t a1, uint32_t a2, uint32_t a3,
                                         uint32_t b0, uint32_t b1) {
    asm volatile(
        "mma.sync.aligned.m16n8k16.row.col.f32.bf16.bf16.f32 "
        "{%0,%1,%2,%3}, {%4,%5,%6,%7}, {%8,%9}, {%0,%1,%2,%3};"
        : "+f"(c0), "+f"(c1), "+f"(c2), "+f"(c3)
        : "r"(a0), "r"(a1), "r"(a2), "r"(a3), "r"(b0), "r"(b1));
}

// ---------------------------------------------------------------------------
// bf16x3 HMMA GEMM with FUSED fp32->bf16 hi/lo split staging.
//   D[M,N] = A[M,K] @ W[K,N] + bias   (A fp32 row-major, W fp32 [K,N])
// 128x128 tile, 8 warps (warp tile 32x64), K-chunk 32, static smem 40960B.
// MODE 0: A=A_in(x), scatter -> g_q/g_k/g_v (q*0.125).
// MODE 1: A=g_y (device-side reference!), dense out.
// ---------------------------------------------------------------------------
#define GP    80                 // smem row pitch bytes (conflict-free ldmatrix)
#define MATB  (128 * GP)         // 10240 per matrix; 4 matrices = 40960B

template <int MODE>
__global__ void __launch_bounds__(256) gemm_hmma(
    const float* __restrict__ A_in, const float* __restrict__ W,
    const float* __restrict__ bias, float* __restrict__ out, int NB)
{
    __shared__ __align__(16) uint8_t smem[4 * MATB];
    const uint32_t sb0 = cvta_smem(smem);
    const int tid = threadIdx.x, wid = tid >> 5, l = tid & 31;
    const int cCol = blockIdx.x, cRow = blockIdx.y;
    const int warp_m = wid & 3, warp_n = wid >> 2;  // 4 x 2 warps
    const int m0 = warp_m * 32, n0v = warp_n * 64;
    const int nbase0 = cCol * 128;

    const int rowA = (l & 7) + 8 * ((l >> 3) & 1), colA8 = l >> 4;
    const int rowB = (l & 7) + 8 * (l >> 4), colB8 = (l >> 3) & 1;

    // device-side selection of the A source (never a host-passed device symbol)
    const float* A = (MODE == 1) ? g_y : A_in;
    const float* Asrc = A + (size_t)cRow * 128 * KDIM;

    float c[2][8][4];
    #pragma unroll
    for (int a = 0; a < 2; a++)
        #pragma unroll
        for (int b = 0; b < 8; b++)
            #pragma unroll
            for (int d = 0; d < 4; d++) c[a][b][d] = 0.f;

    #pragma unroll 1
    for (int cc = 0; cc < 32; cc++) {
        const int k0 = cc * 32;
        __syncthreads();           // previous chunk's reads complete

        // ---- stage A tile [128 x 32] fp32 -> Ah/Al bf16 (k-major rows) ----
        #pragma unroll
        for (int i = 0; i < 4; i++) {
            const int idx = i * 256 + tid;          // 0..1023 float4s
            const int r = idx >> 3, c4 = idx & 7;
            float4 v = *(const float4*)(Asrc + (size_t)r * KDIM + k0 + c4 * 4);
            uint32_t h01 = fpack(v.x, v.y), h23 = fpack(v.z, v.w);
            uint32_t l01 = fpack(v.x - bflow(h01), v.y - bfhigh(h01));
            uint32_t l23 = fpack(v.z - bflow(h23), v.w - bfhigh(h23));
            const uint32_t off = r * GP + c4 * 8;
            *(uint2*)&smem[off]        = make_uint2(h01, h23);
            *(uint2*)&smem[MATB + off] = make_uint2(l01, l23);
        }
        // ---- stage B tile: W[k0..k0+32, nbase0..+128] -> Bh/Bl at [n][k] ----
        #pragma unroll
        for (int i = 0; i < 8; i++) {
            const int idx = i * 256 + tid;          // 0..2047
            const int n = idx & 127, kp = idx >> 7; // kp 0..15 (k pair)
            const float* bp = W + (size_t)(k0 + 2 * kp) * NB + nbase0 + n;
            const float v0 = bp[0], v1 = bp[NB];
            const uint32_t h = fpack(v0, v1);
            const uint32_t lo = fpack(v0 - bflow(h), v1 - bfhigh(h));
            const uint32_t off = n * GP + kp * 4;
            *(uint32_t*)&smem[2 * MATB + off] = h;
            *(uint32_t*)&smem[3 * MATB + off] = lo;
        }
        __syncthreads();

        #pragma unroll
        for (int kk = 0; kk < 32; kk += 16) {
            uint32_t aH[2][4], aL[2][4];
            #pragma unroll
            for (int mf = 0; mf < 2; mf++) {
                uint32_t ao = (m0 + mf * 16 + rowA) * GP + kk * 2 + colA8 * 16;
                ldsm4(sb0 + ao, aH[mf][0], aH[mf][1], aH[mf][2], aH[mf][3]);
                ldsm4(sb0 + MATB + ao, aL[mf][0], aL[mf][1], aL[mf][2], aL[mf][3]);
            }
            #pragma unroll
            for (int g = 0; g < 4; g++) {
                uint32_t bh0, bh1, bh2, bh3, bl0, bl1, bl2, bl3;
                uint32_t bo = (n0v + g * 16 + rowB) * GP + kk * 2 + colB8 * 16;
                ldsm4(sb0 + 2 * MATB + bo, bh0, bh1, bh2, bh3);
                ldsm4(sb0 + 3 * MATB + bo, bl0, bl1, bl2, bl3);
                #pragma unroll
                for (int mf = 0; mf < 2; mf++) {
                    mma16816(c[mf][g*2][0], c[mf][g*2][1], c[mf][g*2][2], c[mf][g*2][3],
                             aH[mf][0], aH[mf][1], aH[mf][2], aH[mf][3], bh0, bh1);
                    mma16816(c[mf][g*2][0], c[mf][g*2][1], c[mf][g*2][2], c[mf][g*2][3],
                             aH[mf][0], aH[mf][1], aH[mf][2], aH[mf][3], bl0, bl1);
                    mma16816(c[mf][g*2][0], c[mf][g*2][1], c[mf][g*2][2], c[mf][g*2][3],
                             aL[mf][0], aL[mf][1], aL[mf][2], aL[mf][3], bh0, bh1);
                    mma16816(c[mf][g*2+1][0], c[mf][g*2+1][1], c[mf][g*2+1][2], c[mf][g*2+1][3],
                             aH[mf][0], aH[mf][1], aH[mf][2], aH[mf][3], bh2, bh3);
                    mma16816(c[mf][g*2+1][0], c[mf][g*2+1][1], c[mf][g*2+1][2], c[mf][g*2+1][3],
                             aH[mf][0], aH[mf][1], aH[mf][2], aH[mf][3], bl2, bl3);
                    mma16816(c[mf][g*2+1][0], c[mf][g*2+1][1], c[mf][g*2+1][2], c[mf][g*2+1][3],
                             aL[mf][0], aL[mf][1], aL[mf][2], aL[mf][3], bh2, bh3);
                }
            }
        }
    }

    // Epilogue
    #pragma unroll
    for (int mf = 0; mf < 2; mf++) {
        const int m = cRow * 128 + m0 + mf * 16 + (l >> 2);
        #pragma unroll
        for (int nf = 0; nf < 8; nf++) {
            const int nc = nbase0 + n0v + nf * 8 + 2 * (l & 3);
            const float b0 = bias[nc], b1 = bias[nc + 1];
            float v00 = c[mf][nf][0] + b0, v01 = c[mf][nf][1] + b1;
            float v10 = c[mf][nf][2] + b0, v11 = c[mf][nf][3] + b1;
            if (MODE == 1) {
                *(float2*)(out + (size_t)m * CC + nc)       = make_float2(v00, v01);
                *(float2*)(out + (size_t)(m + 8) * CC + nc) = make_float2(v10, v11);
            } else {
                const int which = nc >> 10, ccv = nc & 1023;
                const int h = ccv >> 6, db = ccv & 63;
                const int b = m >> 11, tk = m & 2047;
                float* dst = (which == 0 ? g_q : which == 1 ? g_k : g_v);
                size_t o0 = ((((size_t)b * NH + h) * TT + tk) * HD) + db;
                size_t o1 = o0 + 8 * HD;
                if (which == 0) { v00 *= 0.125f; v01 *= 0.125f; v10 *= 0.125f; v11 *= 0.125f; }
                *(float2*)(dst + o0) = make_float2(v00, v01);
                *(float2*)(dst + o1) = make_float2(v10, v11);
            }
        }
    }
}

// ---------------------------------------------------------------------------
// Causal flash attention — fp32 SIMT, VERBATIM round-1/round-14 (proven).
// ---------------------------------------------------------------------------
__global__ void __launch_bounds__(256) attn_kernel()
{
    __shared__ float Qs[BQ * HD];
    __shared__ float KVs[BQ * HD];
    __shared__ float Ps[BQ * BQ];

    const int it  = blockIdx.x;
    const int bh  = blockIdx.y;
    const int tid = threadIdx.x;
    const int tx  = tid & 15;
    const int ty  = tid >> 4;

    const float* Qg = g_q + ((size_t)bh * TT + it * BQ) * HD;
    #pragma unroll
    for (int i = tid; i < BQ * HD / 4; i += 256)
        ((float4*)Qs)[i] = ((const float4*)Qg)[i];

    float O[4][4];
    #pragma unroll
    for (int i = 0; i < 4; i++)
        #pragma unroll
        for (int j = 0; j < 4; j++) O[i][j] = 0.f;
    float mrow[4] = {-INFINITY, -INFINITY, -INFINITY, -INFINITY};
    float lrow[4] = {0.f, 0.f, 0.f, 0.f};

    for (int jt = 0; jt <= it; jt++) {
        __syncthreads();
        const float* Kg = g_k + ((size_t)bh * TT + jt * BQ) * HD;
        #pragma unroll
        for (int i = tid; i < BQ * HD / 4; i += 256)
            ((float4*)KVs)[i] = ((const float4*)Kg)[i];
        __syncthreads();

        float s[4][4];
        #pragma unroll
        for (int i = 0; i < 4; i++)
            #pragma unroll
            for (int j = 0; j < 4; j++) s[i][j] = 0.f;
        #pragma unroll
        for (int kk = 0; kk < HD; kk += 4) {
            float4 a4[4], b4[4];
            #pragma unroll
            for (int i = 0; i < 4; i++)
                a4[i] = *(const float4*)&Qs[(4 * ty + i) * HD + kk];
            #pragma unroll
            for (int j = 0; j < 4; j++)
                b4[j] = *(const float4*)&KVs[(4 * tx + j) * HD + kk];
            #pragma unroll
            for (int i = 0; i < 4; i++)
                #pragma unroll
                for (int j = 0; j < 4; j++)
                    s[i][j] += a4[i].x * b4[j].x + a4[i].y * b4[j].y +
                               a4[i].z * b4[j].z + a4[i].w * b4[j].w;
        }

        if (jt == it) {
            #pragma unroll
            for (int i = 0; i < 4; i++)
                #pragma unroll
                for (int j = 0; j < 4; j++)
                    if ((4 * tx + j) > (4 * ty + i)) s[i][j] = -INFINITY;
        }

        #pragma unroll
        for (int i = 0; i < 4; i++) {
            float mx = fmaxf(fmaxf(s[i][0], s[i][1]), fmaxf(s[i][2], s[i][3]));
            #pragma unroll
            for (int o = 8; o >= 1; o >>= 1)
                mx = fmaxf(mx, __shfl_xor_sync(0xffffffffu, mx, o));
            float mnew = fmaxf(mrow[i], mx);
            float corr = __expf(mrow[i] - mnew);
            float p0 = __expf(s[i][0] - mnew);
            float p1 = __expf(s[i][1] - mnew);
            float p2 = __expf(s[i][2] - mnew);
            float p3 = __expf(s[i][3] - mnew);
            float sum = p0 + p1 + p2 + p3;
            #pragma unroll
            for (int o = 8; o >= 1; o >>= 1)
                sum += __shfl_xor_sync(0xffffffffu, sum, o);
            lrow[i] = lrow[i] * corr + sum;
            mrow[i] = mnew;
            #pragma unroll
            for (int j = 0; j < 4; j++) O[i][j] *= corr;
            *(float4*)&Ps[(4 * ty + i) * BQ + 4 * tx] = make_float4(p0, p1, p2, p3);
        }
        __syncthreads();

        const float* Vg = g_v + ((size_t)bh * TT + jt * BQ) * HD;
        #pragma unroll
        for (int i = tid; i < BQ * HD / 4; i += 256)
            ((float4*)KVs)[i] = ((const float4*)Vg)[i];
        __syncthreads();

        #pragma unroll
        for (int kk = 0; kk < BQ; kk += 4) {
            float4 p4[4], v4[4];
            #pragma unroll
            for (int i = 0; i < 4; i++)
                p4[i] = *(const float4*)&Ps[(4 * ty + i) * BQ + kk];
            #pragma unroll
            for (int k2 = 0; k2 < 4; k2++)
                v4[k2] = *(const float4*)&KVs[(kk + k2) * HD + 4 * tx];
            #pragma unroll
            for (int i = 0; i < 4; i++) {
                O[i][0] += p4[i].x * v4[0].x + p4[i].y * v4[1].x + p4[i].z * v4[2].x + p4[i].w * v4[3].x;
                O[i][1] += p4[i].x * v4[0].y + p4[i].y * v4[1].y + p4[i].z * v4[2].y + p4[i].w * v4[3].y;
                O[i][2] += p4[i].x * v4[0].z + p4[i].y * v4[1].z + p4[i].z * v4[2].z + p4[i].w * v4[3].z;
                O[i][3] += p4[i].x * v4[0].w + p4[i].y * v4[1].w + p4[i].z * v4[2].w + p4[i].w * v4[3].w;
            }
        }
    }

    // Write y in [B,T,C] fp32
    const int b = bh >> 4, h = bh & 15;
    #pragma unroll
    for (int i = 0; i < 4; i++) {
        const int tq = it * BQ + 4 * ty + i;
        const float linv = 1.f / lrow[i];
        float* yp = g_y + ((size_t)b * TT + tq) * CC + h * HD + 4 * tx;
        *(float4*)yp = make_float4(O[i][0] * linv, O[i][1] * linv,
                                   O[i][2] * linv, O[i][3] * linv);
    }
}

// ---------------------------------------------------------------------------
extern "C" void kernel_launch(void* const* d_in, const int* in_sizes, int n_in,
                              void* d_out, int out_size)
{
    const float* x      = (const float*)d_in[0];  // [2,2048,1024]
    const float* w_attn = (const float*)d_in[1];  // [1024,3072]
    const float* b_attn = (const float*)d_in[2];  // [3072]
    const float* w_proj = (const float*)d_in[3];  // [1024,1024]
    const float* b_proj = (const float*)d_in[4];  // [1024]
    float* out = (float*)d_out;                   // [2,2048,1024]

    // 1) QKV projection (HMMA bf16x3, fused split) + scatter to [B,H,T,D]
    gemm_hmma<0><<<dim3(3 * CC / 128, MROWS / 128), 256>>>(
        x, w_attn, b_attn, nullptr, 3 * CC);

    // 2) causal flash attention (fp32 SIMT, proven)
    attn_kernel<<<dim3(TT / BQ, BATCH * NH), 256>>>();

    // 3) output projection (HMMA bf16x3; A = g_y selected INSIDE the kernel)
    gemm_hmma<1><<<dim3(CC / 128, MROWS / 128), 256>>>(
        nullptr, w_proj, b_proj, out, CC);
}

// round 16
// speedup vs baseline: 3.6554x; 3.0366x over previous
#include <cuda_runtime.h>
#include <cuda_bf16.h>
#include <math.h>
#include <stdint.h>

#define BATCH 2
#define TT    2048
#define CC    1024
#define NH    16
#define HD    64
#define KDIM  1024
#define MROWS 4096

// ---------------------------------------------------------------------------
// Device-global scratch — referenced ONLY from device code (proven pattern).
// ---------------------------------------------------------------------------
__device__ float g_q[BATCH * NH * TT * HD];
__device__ float g_k[BATCH * NH * TT * HD];
__device__ float g_v[BATCH * NH * TT * HD];
__device__ float g_y[BATCH * TT * CC];

// ---------------------------------------------------------------------------
// Helpers (scalar-only interfaces)
// ---------------------------------------------------------------------------
__device__ __forceinline__ uint32_t cvta_smem(const void* p) {
    uint32_t a;
    asm("{ .reg .u64 t; cvta.to.shared.u64 t, %1; cvt.u32.u64 %0, t; }"
        : "=r"(a) : "l"(p));
    return a;
}
__device__ __forceinline__ uint32_t fpack(float lo, float hi) {
    uint32_t r;
    asm("cvt.rn.bf16x2.f32 %0, %2, %1;" : "=r"(r) : "f"(lo), "f"(hi));
    return r;
}
__device__ __forceinline__ float bflow(uint32_t u)  { return __uint_as_float(u << 16); }
__device__ __forceinline__ float bfhigh(uint32_t u) { return __uint_as_float(u & 0xffff0000u); }

__device__ __forceinline__ void ldsm4(uint32_t addr, uint32_t& r0, uint32_t& r1,
                                      uint32_t& r2, uint32_t& r3) {
    asm volatile("ldmatrix.sync.aligned.m8n8.x4.shared.b16 {%0,%1,%2,%3}, [%4];"
                 : "=r"(r0), "=r"(r1), "=r"(r2), "=r"(r3) : "r"(addr) : "memory");
}
__device__ __forceinline__ void ldsm4t(uint32_t addr, uint32_t& r0, uint32_t& r1,
                                       uint32_t& r2, uint32_t& r3) {
    asm volatile("ldmatrix.sync.aligned.m8n8.x4.trans.shared.b16 {%0,%1,%2,%3}, [%4];"
                 : "=r"(r0), "=r"(r1), "=r"(r2), "=r"(r3) : "r"(addr) : "memory");
}
__device__ __forceinline__ void mma16816(float& c0, float& c1, float& c2, float& c3,
                                         uint32_t a0, uint32_t a1, uint32_t a2, uint32_t a3,
                                         uint32_t b0, uint32_t b1) {
    asm volatile(
        "mma.sync.aligned.m16n8k16.row.col.f32.bf16.bf16.f32 "
        "{%0,%1,%2,%3}, {%4,%5,%6,%7}, {%8,%9}, {%0,%1,%2,%3};"
        : "+f"(c0), "+f"(c1), "+f"(c2), "+f"(c3)
        : "r"(a0), "r"(a1), "r"(a2), "r"(a3), "r"(b0), "r"(b1));
}

// ---------------------------------------------------------------------------
// bf16x3 HMMA GEMM, fused fp32->bf16 hi/lo split, REGISTER PREFETCH.
//   D[M,N] = A[M,K] @ W[K,N] + bias
// 128x128 tile, 8 warps, K-chunk 32, 40960B static smem.
// MODE 0: A=A_in(x), scatter -> g_q/g_k/g_v (q*0.125). MODE 1: A=g_y, dense.
// ---------------------------------------------------------------------------
#define GP    80
#define MATB  (128 * GP)

template <int MODE>
__global__ void __launch_bounds__(256) gemm_hmma(
    const float* __restrict__ A_in, const float* __restrict__ W,
    const float* __restrict__ bias, float* __restrict__ out, int NB)
{
    __shared__ __align__(16) uint8_t smem[4 * MATB];
    const uint32_t sb0 = cvta_smem(smem);
    const int tid = threadIdx.x, wid = tid >> 5, l = tid & 31;
    const int cCol = blockIdx.x, cRow = blockIdx.y;
    const int warp_m = wid & 3, warp_n = wid >> 2;
    const int m0 = warp_m * 32, n0v = warp_n * 64;
    const int nbase0 = cCol * 128;

    const int rowA = (l & 7) + 8 * ((l >> 3) & 1), colA8 = l >> 4;
    const int rowB = (l & 7) + 8 * (l >> 4), colB8 = (l >> 3) & 1;

    const float* A = (MODE == 1) ? g_y : A_in;
    const float* Asrc = A + (size_t)cRow * 128 * KDIM;

    // per-thread loader coordinates (constant across chunks)
    const int la_r[4] = { (0 * 256 + tid) >> 3, (1 * 256 + tid) >> 3,
                          (2 * 256 + tid) >> 3, (3 * 256 + tid) >> 3 };
    const int la_c = tid & 7;
    const int lb_n = tid & 127;            // same n for all 8 sub-loads? no:
    // B loader: idx = i*256+tid -> n = idx&127, kp = idx>>7
    float4 pa[4];
    float pb0[8], pb1[8];

    float c[2][8][4];
    #pragma unroll
    for (int a = 0; a < 2; a++)
        #pragma unroll
        for (int b = 0; b < 8; b++)
            #pragma unroll
            for (int d = 0; d < 4; d++) c[a][b][d] = 0.f;

    // prologue: LDG chunk 0 into registers
    #pragma unroll
    for (int i = 0; i < 4; i++)
        pa[i] = *(const float4*)(Asrc + (size_t)la_r[i] * KDIM + la_c * 4);
    #pragma unroll
    for (int i = 0; i < 8; i++) {
        const int idx = i * 256 + tid;
        const int n = idx & 127, kp = idx >> 7;
        const float* bp = W + (size_t)(2 * kp) * NB + nbase0 + n;
        pb0[i] = bp[0]; pb1[i] = bp[NB];
    }

    #pragma unroll 1
    for (int cc = 0; cc < 32; cc++) {
        __syncthreads();           // previous chunk's smem reads complete

        // ---- STS current chunk from registers (with hi/lo split) ----
        #pragma unroll
        for (int i = 0; i < 4; i++) {
            float4 v = pa[i];
            uint32_t h01 = fpack(v.x, v.y), h23 = fpack(v.z, v.w);
            uint32_t l01 = fpack(v.x - bflow(h01), v.y - bfhigh(h01));
            uint32_t l23 = fpack(v.z - bflow(h23), v.w - bfhigh(h23));
            const uint32_t off = la_r[i] * GP + la_c * 8;
            *(uint2*)&smem[off]        = make_uint2(h01, h23);
            *(uint2*)&smem[MATB + off] = make_uint2(l01, l23);
        }
        #pragma unroll
        for (int i = 0; i < 8; i++) {
            const int idx = i * 256 + tid;
            const int n = idx & 127, kp = idx >> 7;
            const float v0 = pb0[i], v1 = pb1[i];
            const uint32_t h = fpack(v0, v1);
            const uint32_t lo = fpack(v0 - bflow(h), v1 - bfhigh(h));
            const uint32_t off = n * GP + kp * 4;
            *(uint32_t*)&smem[2 * MATB + off] = h;
            *(uint32_t*)&smem[3 * MATB + off] = lo;
        }
        __syncthreads();

        // ---- prefetch next chunk into registers (hidden under MMAs) ----
        if (cc < 31) {
            const int k0n = (cc + 1) * 32;
            #pragma unroll
            for (int i = 0; i < 4; i++)
                pa[i] = *(const float4*)(Asrc + (size_t)la_r[i] * KDIM + k0n + la_c * 4);
            #pragma unroll
            for (int i = 0; i < 8; i++) {
                const int idx = i * 256 + tid;
                const int n = idx & 127, kp = idx >> 7;
                const float* bp = W + (size_t)(k0n + 2 * kp) * NB + nbase0 + n;
                pb0[i] = bp[0]; pb1[i] = bp[NB];
            }
        }

        // ---- MMAs on current chunk ----
        #pragma unroll
        for (int kk = 0; kk < 32; kk += 16) {
            uint32_t aH[2][4], aL[2][4];
            #pragma unroll
            for (int mf = 0; mf < 2; mf++) {
                uint32_t ao = (m0 + mf * 16 + rowA) * GP + kk * 2 + colA8 * 16;
                ldsm4(sb0 + ao, aH[mf][0], aH[mf][1], aH[mf][2], aH[mf][3]);
                ldsm4(sb0 + MATB + ao, aL[mf][0], aL[mf][1], aL[mf][2], aL[mf][3]);
            }
            #pragma unroll
            for (int g = 0; g < 4; g++) {
                uint32_t bh0, bh1, bh2, bh3, bl0, bl1, bl2, bl3;
                uint32_t bo = (n0v + g * 16 + rowB) * GP + kk * 2 + colB8 * 16;
                ldsm4(sb0 + 2 * MATB + bo, bh0, bh1, bh2, bh3);
                ldsm4(sb0 + 3 * MATB + bo, bl0, bl1, bl2, bl3);
                #pragma unroll
                for (int mf = 0; mf < 2; mf++) {
                    mma16816(c[mf][g*2][0], c[mf][g*2][1], c[mf][g*2][2], c[mf][g*2][3],
                             aH[mf][0], aH[mf][1], aH[mf][2], aH[mf][3], bh0, bh1);
                    mma16816(c[mf][g*2][0], c[mf][g*2][1], c[mf][g*2][2], c[mf][g*2][3],
                             aH[mf][0], aH[mf][1], aH[mf][2], aH[mf][3], bl0, bl1);
                    mma16816(c[mf][g*2][0], c[mf][g*2][1], c[mf][g*2][2], c[mf][g*2][3],
                             aL[mf][0], aL[mf][1], aL[mf][2], aL[mf][3], bh0, bh1);
                    mma16816(c[mf][g*2+1][0], c[mf][g*2+1][1], c[mf][g*2+1][2], c[mf][g*2+1][3],
                             aH[mf][0], aH[mf][1], aH[mf][2], aH[mf][3], bh2, bh3);
                    mma16816(c[mf][g*2+1][0], c[mf][g*2+1][1], c[mf][g*2+1][2], c[mf][g*2+1][3],
                             aH[mf][0], aH[mf][1], aH[mf][2], aH[mf][3], bl2, bl3);
                    mma16816(c[mf][g*2+1][0], c[mf][g*2+1][1], c[mf][g*2+1][2], c[mf][g*2+1][3],
                             aL[mf][0], aL[mf][1], aL[mf][2], aL[mf][3], bh2, bh3);
                }
            }
        }
    }

    // Epilogue (proven)
    #pragma unroll
    for (int mf = 0; mf < 2; mf++) {
        const int m = cRow * 128 + m0 + mf * 16 + (l >> 2);
        #pragma unroll
        for (int nf = 0; nf < 8; nf++) {
            const int nc = nbase0 + n0v + nf * 8 + 2 * (l & 3);
            const float b0 = bias[nc], b1 = bias[nc + 1];
            float v00 = c[mf][nf][0] + b0, v01 = c[mf][nf][1] + b1;
            float v10 = c[mf][nf][2] + b0, v11 = c[mf][nf][3] + b1;
            if (MODE == 1) {
                *(float2*)(out + (size_t)m * CC + nc)       = make_float2(v00, v01);
                *(float2*)(out + (size_t)(m + 8) * CC + nc) = make_float2(v10, v11);
            } else {
                const int which = nc >> 10, ccv = nc & 1023;
                const int h = ccv >> 6, db = ccv & 63;
                const int b = m >> 11, tk = m & 2047;
                float* dst = (which == 0 ? g_q : which == 1 ? g_k : g_v);
                size_t o0 = ((((size_t)b * NH + h) * TT + tk) * HD) + db;
                size_t o1 = o0 + 8 * HD;
                if (which == 0) { v00 *= 0.125f; v01 *= 0.125f; v10 *= 0.125f; v11 *= 0.125f; }
                *(float2*)(dst + o0) = make_float2(v00, v01);
                *(float2*)(dst + o1) = make_float2(v10, v11);
            }
        }
    }
}

// ---------------------------------------------------------------------------
// Flash attention, HMMA bf16x3. 128 threads (4 warps x 16 q-rows), 64-key tiles.
// STATIC smem 36864B: 4 buffers [64 x 144B]: Kh (Q hi first), Kl (Q lo), Vh, Vl.
// Q fragments held in registers for the whole kernel. fp32 y epilogue.
// ---------------------------------------------------------------------------
#define AP 144
#define ABUF (64 * AP)

__global__ void __launch_bounds__(128) attn_hmma()
{
    __shared__ __align__(16) uint8_t sm[4 * ABUF];   // 36864B static
    const uint32_t s0 = cvta_smem(sm);
    const uint32_t sKh = s0, sKl = s0 + ABUF;
    const uint32_t sVh = s0 + 2 * ABUF, sVl = s0 + 3 * ABUF;

    const int tid = threadIdx.x, w = tid >> 5, l = tid & 31;
    const int it = (int)gridDim.x - 1 - blockIdx.x;   // heavy tiles first
    const int bh = blockIdx.y;

    const int rowA = (l & 7) + 8 * ((l >> 3) & 1), colA8 = l >> 4;
    const int rowB = (l & 7) + 8 * (l >> 4), colB8 = (l >> 3) & 1;

    // ---- stage Q tile (fp32 -> bf16 hi/lo) into buffers 0/1 ----
    const float* Qg = g_q + ((size_t)bh * TT + it * 64) * HD;
    #pragma unroll
    for (int i = 0; i < 8; i++) {
        int idx = tid + i * 128;            // 1024 float4s
        int r = idx >> 4, d4 = idx & 15;
        float4 v = ((const float4*)Qg)[r * 16 + d4];
        uint32_t h01 = fpack(v.x, v.y), h23 = fpack(v.z, v.w);
        uint32_t l01 = fpack(v.x - bflow(h01), v.y - bfhigh(h01));
        uint32_t l23 = fpack(v.z - bflow(h23), v.w - bfhigh(h23));
        uint32_t off = r * AP + d4 * 8;
        *(uint2*)(sm + off)        = make_uint2(h01, h23);
        *(uint2*)(sm + ABUF + off) = make_uint2(l01, l23);
    }
    __syncthreads();

    // ---- extract Q a-frags (held in registers all kernel) ----
    uint32_t aQh[4][4], aQl[4][4];
    const int q0 = w * 16;
    #pragma unroll
    for (int dc = 0; dc < 4; dc++) {
        uint32_t off = (q0 + rowA) * AP + dc * 32 + colA8 * 16;
        ldsm4(sKh + off, aQh[dc][0], aQh[dc][1], aQh[dc][2], aQh[dc][3]);
        ldsm4(sKl + off, aQl[dc][0], aQl[dc][1], aQl[dc][2], aQl[dc][3]);
    }

    float o[8][4];
    #pragma unroll
    for (int g = 0; g < 8; g++)
        #pragma unroll
        for (int d = 0; d < 4; d++) o[g][d] = 0.f;
    float m0r = -INFINITY, m1r = -INFINITY, l0r = 0.f, l1r = 0.f;

    #pragma unroll 1
    for (int jt = 0; jt <= it; jt++) {
        __syncthreads();   // Q frags extracted (jt=0) / prev tile reads done
        const float* Kg = g_k + ((size_t)bh * TT + jt * 64) * HD;
        const float* Vg = g_v + ((size_t)bh * TT + jt * 64) * HD;
        #pragma unroll
        for (int i = 0; i < 16; i++) {
            const int mat = i >> 3;         // 0=K, 1=V (compile-time)
            int idx = tid + (i & 7) * 128;
            int r = idx >> 4, d4 = idx & 15;
            const float* src = (mat ? Vg : Kg) + r * 64 + d4 * 4;
            float4 v = *(const float4*)src;
            uint32_t h01 = fpack(v.x, v.y), h23 = fpack(v.z, v.w);
            uint32_t l01 = fpack(v.x - bflow(h01), v.y - bfhigh(h01));
            uint32_t l23 = fpack(v.z - bflow(h23), v.w - bfhigh(h23));
            uint32_t off = r * AP + d4 * 8;
            *(uint2*)(sm + (mat ? 2 * ABUF : 0) + off)        = make_uint2(h01, h23);
            *(uint2*)(sm + (mat ? 3 * ABUF : ABUF) + off)     = make_uint2(l01, l23);
        }
        __syncthreads();

        // ---- S = Q K^T (bf16x3) ----
        float c[8][4];
        #pragma unroll
        for (int g = 0; g < 8; g++)
            #pragma unroll
            for (int d = 0; d < 4; d++) c[g][d] = 0.f;
        #pragma unroll
        for (int dc = 0; dc < 4; dc++) {
            #pragma unroll
            for (int n2 = 0; n2 < 4; n2++) {
                uint32_t bh0, bh1, bh2, bh3, bl0, bl1, bl2, bl3;
                uint32_t off = (n2 * 16 + rowB) * AP + dc * 32 + colB8 * 16;
                ldsm4(sKh + off, bh0, bh1, bh2, bh3);
                ldsm4(sKl + off, bl0, bl1, bl2, bl3);
                mma16816(c[n2*2][0], c[n2*2][1], c[n2*2][2], c[n2*2][3],
                         aQh[dc][0], aQh[dc][1], aQh[dc][2], aQh[dc][3], bh0, bh1);
                mma16816(c[n2*2][0], c[n2*2][1], c[n2*2][2], c[n2*2][3],
                         aQh[dc][0], aQh[dc][1], aQh[dc][2], aQh[dc][3], bl0, bl1);
                mma16816(c[n2*2][0], c[n2*2][1], c[n2*2][2], c[n2*2][3],
                         aQl[dc][0], aQl[dc][1], aQl[dc][2], aQl[dc][3], bh0, bh1);
                mma16816(c[n2*2+1][0], c[n2*2+1][1], c[n2*2+1][2], c[n2*2+1][3],
                         aQh[dc][0], aQh[dc][1], aQh[dc][2], aQh[dc][3], bh2, bh3);
                mma16816(c[n2*2+1][0], c[n2*2+1][1], c[n2*2+1][2], c[n2*2+1][3],
                         aQh[dc][0], aQh[dc][1], aQh[dc][2], aQh[dc][3], bl2, bl3);
                mma16816(c[n2*2+1][0], c[n2*2+1][1], c[n2*2+1][2], c[n2*2+1][3],
                         aQl[dc][0], aQl[dc][1], aQl[dc][2], aQl[dc][3], bh2, bh3);
            }
        }

        // causal mask (diagonal tile only)
        if (jt == it) {
            const int r0 = w * 16 + (l >> 2), r1 = r0 + 8;
            #pragma unroll
            for (int g = 0; g < 8; g++) {
                const int col = g * 8 + 2 * (l & 3);
                if (col > r0)     c[g][0] = -INFINITY;
                if (col + 1 > r0) c[g][1] = -INFINITY;
                if (col > r1)     c[g][2] = -INFINITY;
                if (col + 1 > r1) c[g][3] = -INFINITY;
            }
        }

        // ---- online softmax (rows owned by 4 lanes: xor 1,2) ----
        float mx0 = -INFINITY, mx1 = -INFINITY;
        #pragma unroll
        for (int g = 0; g < 8; g++) {
            mx0 = fmaxf(mx0, fmaxf(c[g][0], c[g][1]));
            mx1 = fmaxf(mx1, fmaxf(c[g][2], c[g][3]));
        }
        mx0 = fmaxf(mx0, __shfl_xor_sync(0xffffffffu, mx0, 1));
        mx0 = fmaxf(mx0, __shfl_xor_sync(0xffffffffu, mx0, 2));
        mx1 = fmaxf(mx1, __shfl_xor_sync(0xffffffffu, mx1, 1));
        mx1 = fmaxf(mx1, __shfl_xor_sync(0xffffffffu, mx1, 2));
        const float mn0 = fmaxf(m0r, mx0), mn1 = fmaxf(m1r, mx1);
        const float cr0 = __expf(m0r - mn0), cr1 = __expf(m1r - mn1);
        m0r = mn0; m1r = mn1;
        float sum0 = 0.f, sum1 = 0.f;
        #pragma unroll
        for (int g = 0; g < 8; g++) {
            c[g][0] = __expf(c[g][0] - mn0); sum0 += c[g][0];
            c[g][1] = __expf(c[g][1] - mn0); sum0 += c[g][1];
            c[g][2] = __expf(c[g][2] - mn1); sum1 += c[g][2];
            c[g][3] = __expf(c[g][3] - mn1); sum1 += c[g][3];
        }
        sum0 += __shfl_xor_sync(0xffffffffu, sum0, 1);
        sum0 += __shfl_xor_sync(0xffffffffu, sum0, 2);
        sum1 += __shfl_xor_sync(0xffffffffu, sum1, 1);
        sum1 += __shfl_xor_sync(0xffffffffu, sum1, 2);
        l0r = l0r * cr0 + sum0;
        l1r = l1r * cr1 + sum1;
        #pragma unroll
        for (int g = 0; g < 8; g++) {
            o[g][0] *= cr0; o[g][1] *= cr0; o[g][2] *= cr1; o[g][3] *= cr1;
        }

        // ---- O += P V (P hi/lo from registers, V via trans ldmatrix) ----
        #pragma unroll 1
        for (int kc = 0; kc < 4; kc++) {
            uint32_t aPh0, aPh1, aPh2, aPh3, aPl0, aPl1, aPl2, aPl3;
            {
                uint32_t h;
                h = fpack(c[kc*2][0], c[kc*2][1]); aPh0 = h;
                aPl0 = fpack(c[kc*2][0] - bflow(h), c[kc*2][1] - bfhigh(h));
                h = fpack(c[kc*2][2], c[kc*2][3]); aPh1 = h;
                aPl1 = fpack(c[kc*2][2] - bflow(h), c[kc*2][3] - bfhigh(h));
                h = fpack(c[kc*2+1][0], c[kc*2+1][1]); aPh2 = h;
                aPl2 = fpack(c[kc*2+1][0] - bflow(h), c[kc*2+1][1] - bfhigh(h));
                h = fpack(c[kc*2+1][2], c[kc*2+1][3]); aPh3 = h;
                aPl3 = fpack(c[kc*2+1][2] - bflow(h), c[kc*2+1][3] - bfhigh(h));
            }
            #pragma unroll
            for (int d2 = 0; d2 < 4; d2++) {
                uint32_t bh0, bh1, bh2, bh3, bl0, bl1, bl2, bl3;
                uint32_t off = (kc * 16 + rowA) * AP + d2 * 32 + colA8 * 16;
                ldsm4t(sVh + off, bh0, bh1, bh2, bh3);
                ldsm4t(sVl + off, bl0, bl1, bl2, bl3);
                mma16816(o[d2*2][0], o[d2*2][1], o[d2*2][2], o[d2*2][3],
                         aPh0, aPh1, aPh2, aPh3, bh0, bh1);
                mma16816(o[d2*2][0], o[d2*2][1], o[d2*2][2], o[d2*2][3],
                         aPh0, aPh1, aPh2, aPh3, bl0, bl1);
                mma16816(o[d2*2][0], o[d2*2][1], o[d2*2][2], o[d2*2][3],
                         aPl0, aPl1, aPl2, aPl3, bh0, bh1);
                mma16816(o[d2*2+1][0], o[d2*2+1][1], o[d2*2+1][2], o[d2*2+1][3],
                         aPh0, aPh1, aPh2, aPh3, bh2, bh3);
                mma16816(o[d2*2+1][0], o[d2*2+1][1], o[d2*2+1][2], o[d2*2+1][3],
                         aPh0, aPh1, aPh2, aPh3, bl2, bl3);
                mma16816(o[d2*2+1][0], o[d2*2+1][1], o[d2*2+1][2], o[d2*2+1][3],
                         aPl0, aPl1, aPl2, aPl3, bh2, bh3);
            }
        }
    }

    // ---- epilogue: fp32 y in [B,T,C] ----
    const float li0 = 1.f / l0r, li1 = 1.f / l1r;
    const int b = bh >> 4, h = bh & 15;
    const int tq0 = it * 64 + w * 16 + (l >> 2), tq1 = tq0 + 8;
    float* y0 = g_y + ((size_t)b * TT + tq0) * CC + h * HD;
    float* y1 = g_y + ((size_t)b * TT + tq1) * CC + h * HD;
    #pragma unroll
    for (int g = 0; g < 8; g++) {
        const int col = g * 8 + 2 * (l & 3);
        *(float2*)(y0 + col) = make_float2(o[g][0] * li0, o[g][1] * li0);
        *(float2*)(y1 + col) = make_float2(o[g][2] * li1, o[g][3] * li1);
    }
}

// ---------------------------------------------------------------------------
extern "C" void kernel_launch(void* const* d_in, const int* in_sizes, int n_in,
                              void* d_out, int out_size)
{
    const float* x      = (const float*)d_in[0];  // [2,2048,1024]
    const float* w_attn = (const float*)d_in[1];  // [1024,3072]
    const float* b_attn = (const float*)d_in[2];  // [3072]
    const float* w_proj = (const float*)d_in[3];  // [1024,1024]
    const float* b_proj = (const float*)d_in[4];  // [1024]
    float* out = (float*)d_out;                   // [2,2048,1024]

    // 1) QKV projection (HMMA bf16x3 + prefetch) + scatter to [B,H,T,D]
    gemm_hmma<0><<<dim3(3 * CC / 128, MROWS / 128), 256>>>(
        x, w_attn, b_attn, nullptr, 3 * CC);

    // 2) causal flash attention (HMMA bf16x3)
    attn_hmma<<<dim3(TT / 64, BATCH * NH), 128>>>();

    // 3) output projection (HMMA bf16x3; A = g_y selected inside the kernel)
    gemm_hmma<1><<<dim3(CC / 128, MROWS / 128), 256>>>(
        nullptr, w_proj, b_proj, out, CC);
}